// round 2
// baseline (speedup 1.0000x reference)
#include <cuda_runtime.h>
#include <cuda_bf16.h>

#define NN   2048
#define RBF  32
#define TPB  256

// Fused F1-filter kernel:
//   hidden[a,b,h] = softplus(rbf[a,b,:]·W1[:,h] + b1[h])
//   radial[a,b]   = hidden·W2 + b2, masked where |rij| < 1e-8
//   out[a,:]     += radial * (unit(rij[a,b]) x layer_input[b])
// One block per 'a'; each thread walks b = tid, tid+TPB, ...
__global__ __launch_bounds__(TPB) void f1o1_kernel(
    const float* __restrict__ layer_input,  // [NN,1,3]
    const float* __restrict__ rbf,          // [NN,NN,RBF]
    const float* __restrict__ rij,          // [NN,NN,3]
    const float* __restrict__ W1,           // [RBF,RBF] (k,h)
    const float* __restrict__ b1,           // [RBF]
    const float* __restrict__ W2,           // [RBF,1]
    const float* __restrict__ b2,           // [1]
    float* __restrict__ out)                // [NN,1,3]
{
    __shared__ __align__(16) float w1t[RBF][RBF];  // transposed: [h][k]
    __shared__ float w2s[RBF];
    __shared__ float b1s[RBF];
    __shared__ __align__(16) float Ls[NN * 3];     // layer_input cache (24 KB)
    __shared__ float red[3][TPB];

    const int tid = threadIdx.x;
    const int a   = blockIdx.x;

    // Stage weights (transpose W1 so the k-dim is contiguous per h-row -> float4)
    for (int i = tid; i < RBF * RBF; i += TPB) {
        int k = i / RBF, h = i % RBF;
        w1t[h][k] = W1[i];
    }
    if (tid < RBF) { w2s[tid] = W2[tid]; b1s[tid] = b1[tid]; }
    for (int i = tid; i < NN * 3; i += TPB) Ls[i] = layer_input[i];
    __syncthreads();

    const float bias2 = b2[0];
    float acc0 = 0.f, acc1 = 0.f, acc2 = 0.f;

    #pragma unroll 1
    for (int b = tid; b < NN; b += TPB) {
        // x = rbf[a,b,:] into registers (8x float4 = 128B contiguous)
        const float4* xp = reinterpret_cast<const float4*>(
            rbf + ((size_t)a * NN + b) * RBF);
        float4 xv[8];
        #pragma unroll
        for (int i = 0; i < 8; i++) xv[i] = xp[i];

        float radial = bias2;
        #pragma unroll
        for (int h = 0; h < RBF; h++) {
            float s = b1s[h];
            const float4* wp = reinterpret_cast<const float4*>(&w1t[h][0]);
            #pragma unroll
            for (int i = 0; i < 8; i++) {
                float4 w = wp[i];   // smem broadcast (all lanes same addr)
                s = fmaf(xv[i].x, w.x, s);
                s = fmaf(xv[i].y, w.y, s);
                s = fmaf(xv[i].z, w.z, s);
                s = fmaf(xv[i].w, w.w, s);
            }
            // softplus(s) = max(s,0) + log(1 + exp(-|s|)), fast intrinsics
            float e  = __expf(-fabsf(s));
            float sp = fmaxf(s, 0.f) + __logf(1.f + e);
            radial = fmaf(w2s[h], sp, radial);
        }

        // rij, mask, unit vector
        const float* rp = rij + ((size_t)a * NN + b) * 3;
        float rx = rp[0], ry = rp[1], rz = rp[2];
        float d2  = fmaf(rx, rx, fmaf(ry, ry, rz * rz));
        float inv = rsqrtf(fmaxf(d2, 1e-8f));     // norm_with_epsilon
        float m   = (d2 < 1e-16f) ? 0.f : radial; // dij < 1e-8 mask
        float s   = m * inv;
        float ux = rx * s, uy = ry * s, uz = rz * s;

        float lx = Ls[b * 3 + 0], ly = Ls[b * 3 + 1], lz = Ls[b * 3 + 2];
        // out_i += (u x L)_i
        acc0 = fmaf(uy, lz, acc0); acc0 = fmaf(-uz, ly, acc0);
        acc1 = fmaf(uz, lx, acc1); acc1 = fmaf(-ux, lz, acc1);
        acc2 = fmaf(ux, ly, acc2); acc2 = fmaf(-uy, lx, acc2);
    }

    // Block reduction of the 3-vector
    red[0][tid] = acc0; red[1][tid] = acc1; red[2][tid] = acc2;
    __syncthreads();
    #pragma unroll
    for (int s = TPB / 2; s >= 1; s >>= 1) {
        if (tid < s) {
            red[0][tid] += red[0][tid + s];
            red[1][tid] += red[1][tid + s];
            red[2][tid] += red[2][tid + s];
        }
        __syncthreads();
    }
    if (tid == 0) {
        out[a * 3 + 0] = red[0][0];
        out[a * 3 + 1] = red[1][0];
        out[a * 3 + 2] = red[2][0];
    }
}

extern "C" void kernel_launch(void* const* d_in, const int* in_sizes, int n_in,
                              void* d_out, int out_size) {
    const float* layer_input = (const float*)d_in[0];
    const float* rbf         = (const float*)d_in[1];
    const float* rij         = (const float*)d_in[2];
    const float* W1          = (const float*)d_in[3];
    const float* b1          = (const float*)d_in[4];
    const float* W2          = (const float*)d_in[5];
    const float* b2          = (const float*)d_in[6];
    float* out = (float*)d_out;

    f1o1_kernel<<<NN, TPB>>>(layer_input, rbf, rij, W1, b1, W2, b2, out);
}

// round 3
// speedup vs baseline: 1.7685x; 1.7685x over previous
#include <cuda_runtime.h>
#include <cuda_bf16.h>

#define NN   2048
#define RBF  32
#define TPB  256

// ---- f32x2 packed helpers (sm_103a FFMA2 path) ----
__device__ __forceinline__ unsigned long long pack2(float lo, float hi) {
    unsigned long long r;
    asm("mov.b64 %0, {%1, %2};"
        : "=l"(r) : "r"(__float_as_uint(lo)), "r"(__float_as_uint(hi)));
    return r;
}
__device__ __forceinline__ void unpack2(unsigned long long v, float& lo, float& hi) {
    unsigned int l, h;
    asm("mov.b64 {%0, %1}, %2;" : "=r"(l), "=r"(h) : "l"(v));
    lo = __uint_as_float(l); hi = __uint_as_float(h);
}
__device__ __forceinline__ void ffma2(unsigned long long& d,
                                      unsigned long long a, unsigned long long b) {
    asm("fma.rn.f32x2 %0, %1, %2, %3;" : "=l"(d) : "l"(a), "l"(b), "l"(d));
}

// Fused F1-filter: per pair (a,b): radial = W2·softplus(W1·rbf + b1) + b2,
// masked at zero distance; out[a] += radial * unit(rij) x layer_input[b].
// One block per a, thread-per-b, h-pairs packed in f32x2 accumulators.
__global__ __launch_bounds__(TPB, 2) void f1o1_kernel(
    const float* __restrict__ layer_input,  // [NN,1,3]
    const float* __restrict__ rbf,          // [NN,NN,RBF]
    const float* __restrict__ rij,          // [NN,NN,3]
    const float* __restrict__ W1,           // [RBF,RBF] (k,h) row-major
    const float* __restrict__ b1,           // [RBF]
    const float* __restrict__ W2,           // [RBF,1]
    const float* __restrict__ b2,           // [1]
    float* __restrict__ out)                // [NN,1,3]
{
    __shared__ __align__(16) float w1s[RBF * RBF];  // natural [k][h]
    __shared__ __align__(16) float b1s[RBF];
    __shared__ __align__(16) float w2s[RBF];
    __shared__ __align__(16) float Ls[NN * 3];      // layer_input cache (24 KB)
    __shared__ float redbuf[3][TPB / 32];

    const int tid = threadIdx.x;
    const int a   = blockIdx.x;

    for (int i = tid; i < RBF * RBF; i += TPB) w1s[i] = W1[i];
    if (tid < RBF) { b1s[tid] = b1[tid]; w2s[tid] = W2[tid]; }
    for (int i = tid; i < NN * 3; i += TPB) Ls[i] = layer_input[i];
    __syncthreads();

    const float bias2 = b2[0];
    const unsigned long long* b1u = (const unsigned long long*)b1s;
    const unsigned long long* w2u = (const unsigned long long*)w2s;

    float o0 = 0.f, o1 = 0.f, o2 = 0.f;

    #pragma unroll 1
    for (int b = tid; b < NN; b += TPB) {
        // x = rbf[a,b,:] (128B contiguous, 8x LDG.128)
        float x[RBF];
        const float4* xp = (const float4*)(rbf + ((size_t)a * NN + b) * RBF);
        #pragma unroll
        for (int i = 0; i < 8; i++) ((float4*)x)[i] = xp[i];

        // acc[j] packs hidden pre-activations for h = 2j, 2j+1
        unsigned long long acc[RBF / 2];
        #pragma unroll
        for (int j = 0; j < RBF / 2; j++) acc[j] = b1u[j];

        #pragma unroll
        for (int k = 0; k < RBF; k++) {
            unsigned long long xd = pack2(x[k], x[k]);
            const ulonglong2* wp = (const ulonglong2*)(w1s + k * RBF);
            #pragma unroll
            for (int jj = 0; jj < 8; jj++) {
                ulonglong2 w = wp[jj];   // LDS.128 broadcast: two f32x2 operands
                ffma2(acc[jj * 2 + 0], xd, w.x);
                ffma2(acc[jj * 2 + 1], xd, w.y);
            }
        }

        // softplus + second dense (packed)
        unsigned long long rad2 = 0ULL;  // {0.f, 0.f}
        #pragma unroll
        for (int j = 0; j < RBF / 2; j++) {
            float s0, s1; unpack2(acc[j], s0, s1);
            float sp0 = fmaxf(s0, 0.f) + __logf(1.f + __expf(-fabsf(s0)));
            float sp1 = fmaxf(s1, 0.f) + __logf(1.f + __expf(-fabsf(s1)));
            ffma2(rad2, pack2(sp0, sp1), w2u[j]);
        }
        float r0, r1; unpack2(rad2, r0, r1);
        float radial = bias2 + r0 + r1;

        // mask + unit vector + cross with layer_input
        const float* rp = rij + ((size_t)a * NN + b) * 3;
        float rx = rp[0], ry = rp[1], rz = rp[2];
        float d2  = fmaf(rx, rx, fmaf(ry, ry, rz * rz));
        float inv = rsqrtf(fmaxf(d2, 1e-8f));       // norm_with_epsilon
        float m   = (d2 < 1e-16f) ? 0.f : radial;   // dij < 1e-8 mask
        float s   = m * inv;
        float ux = rx * s, uy = ry * s, uz = rz * s;
        float lx = Ls[b * 3 + 0], ly = Ls[b * 3 + 1], lz = Ls[b * 3 + 2];
        o0 = fmaf(uy, lz, o0); o0 = fmaf(-uz, ly, o0);
        o1 = fmaf(uz, lx, o1); o1 = fmaf(-ux, lz, o1);
        o2 = fmaf(ux, ly, o2); o2 = fmaf(-uy, lx, o2);
    }

    // intra-warp reduce, then cross-warp via smem
    #pragma unroll
    for (int off = 16; off > 0; off >>= 1) {
        o0 += __shfl_down_sync(0xffffffffu, o0, off);
        o1 += __shfl_down_sync(0xffffffffu, o1, off);
        o2 += __shfl_down_sync(0xffffffffu, o2, off);
    }
    const int warp = tid >> 5, lane = tid & 31;
    if (lane == 0) { redbuf[0][warp] = o0; redbuf[1][warp] = o1; redbuf[2][warp] = o2; }
    __syncthreads();
    if (tid == 0) {
        float s0 = 0.f, s1 = 0.f, s2 = 0.f;
        #pragma unroll
        for (int w = 0; w < TPB / 32; w++) {
            s0 += redbuf[0][w]; s1 += redbuf[1][w]; s2 += redbuf[2][w];
        }
        out[a * 3 + 0] = s0;
        out[a * 3 + 1] = s1;
        out[a * 3 + 2] = s2;
    }
}

extern "C" void kernel_launch(void* const* d_in, const int* in_sizes, int n_in,
                              void* d_out, int out_size) {
    const float* layer_input = (const float*)d_in[0];
    const float* rbf         = (const float*)d_in[1];
    const float* rij         = (const float*)d_in[2];
    const float* W1          = (const float*)d_in[3];
    const float* b1          = (const float*)d_in[4];
    const float* W2          = (const float*)d_in[5];
    const float* b2          = (const float*)d_in[6];
    float* out = (float*)d_out;

    f1o1_kernel<<<NN, TPB>>>(layer_input, rbf, rij, W1, b1, W2, b2, out);
}

// round 4
// speedup vs baseline: 13.2868x; 7.5130x over previous
#include <cuda_runtime.h>
#include <cuda_bf16.h>

#define NN   2048
#define RBF  32
#define TPB  256

// ---- f32x2 packed helpers (sm_103a FFMA2 path) ----
__device__ __forceinline__ unsigned long long pack2(float lo, float hi) {
    unsigned long long r;
    asm("mov.b64 %0, {%1, %2};"
        : "=l"(r) : "r"(__float_as_uint(lo)), "r"(__float_as_uint(hi)));
    return r;
}
__device__ __forceinline__ void unpack2(unsigned long long v, float& lo, float& hi) {
    unsigned int l, h;
    asm("mov.b64 {%0, %1}, %2;" : "=r"(l), "=r"(h) : "l"(v));
    lo = __uint_as_float(l); hi = __uint_as_float(h);
}
__device__ __forceinline__ void ffma2(unsigned long long& d,
                                      unsigned long long a, unsigned long long b) {
    asm("fma.rn.f32x2 %0, %1, %2, %3;" : "=l"(d) : "l"(a), "l"(b), "l"(d));
}

// Fused F1-filter: per pair (a,b): radial = W2·softplus(W1·rbf + b1) + b2,
// masked at zero distance; out[a] += radial * unit(rij) x layer_input[b].
// One block per a, thread-per-b. rbf row streamed in float4 chunks (double
// buffered, unroll 1) so only acc[16] f32x2 accumulators stay live -> no spills.
__global__ __launch_bounds__(TPB, 3) void f1o1_kernel(
    const float* __restrict__ layer_input,  // [NN,1,3]
    const float* __restrict__ rbf,          // [NN,NN,RBF]
    const float* __restrict__ rij,          // [NN,NN,3]
    const float* __restrict__ W1,           // [RBF,RBF] (k,h) row-major
    const float* __restrict__ b1,           // [RBF]
    const float* __restrict__ W2,           // [RBF,1]
    const float* __restrict__ b2,           // [1]
    float* __restrict__ out)                // [NN,1,3]
{
    __shared__ __align__(16) float w1s[RBF * RBF];  // natural [k][h]
    __shared__ __align__(16) float b1s[RBF];
    __shared__ __align__(16) float w2s[RBF];
    __shared__ __align__(16) float Ls[NN * 3];      // layer_input cache (24 KB)
    __shared__ float redbuf[3][TPB / 32];

    const int tid = threadIdx.x;
    const int a   = blockIdx.x;

    for (int i = tid; i < RBF * RBF; i += TPB) w1s[i] = W1[i];
    if (tid < RBF) { b1s[tid] = b1[tid]; w2s[tid] = W2[tid]; }
    for (int i = tid; i < NN * 3; i += TPB) Ls[i] = layer_input[i];
    __syncthreads();

    const float bias2 = b2[0];
    const unsigned long long* b1u = (const unsigned long long*)b1s;
    const unsigned long long* w2u = (const unsigned long long*)w2s;

    float o0 = 0.f, o1 = 0.f, o2 = 0.f;

    #pragma unroll 1
    for (int b = tid; b < NN; b += TPB) {
        const float4* xp = (const float4*)(rbf + ((size_t)a * NN + b) * RBF);

        // acc[j] packs hidden pre-activations for h = 2j, 2j+1
        unsigned long long acc[RBF / 2];
        #pragma unroll
        for (int j = 0; j < RBF / 2; j++) acc[j] = b1u[j];

        // Stream x in 4-float chunks, double buffered. unroll 1 keeps only
        // cur/nxt live (8 regs) instead of all 32 x values.
        float4 cur = xp[0];
        #pragma unroll 1
        for (int i = 0; i < 8; i++) {
            float4 nxt = xp[(i + 1) & 7];   // last iter re-reads chunk 0 (L1 hit)
            float xk0 = cur.x, xk1 = cur.y, xk2 = cur.z, xk3 = cur.w;
            const ulonglong2* wp = (const ulonglong2*)(w1s + i * 4 * RBF);
            #pragma unroll
            for (int kk = 0; kk < 4; kk++) {
                float xv = (kk == 0) ? xk0 : (kk == 1) ? xk1 : (kk == 2) ? xk2 : xk3;
                unsigned long long xd = pack2(xv, xv);
                #pragma unroll
                for (int jj = 0; jj < 8; jj++) {
                    ulonglong2 w = wp[kk * 8 + jj];  // LDS.128 broadcast
                    ffma2(acc[jj * 2 + 0], xd, w.x);
                    ffma2(acc[jj * 2 + 1], xd, w.y);
                }
            }
            cur = nxt;
        }

        // softplus + second dense (packed)
        unsigned long long rad2 = 0ULL;  // {0.f, 0.f}
        #pragma unroll
        for (int j = 0; j < RBF / 2; j++) {
            float s0, s1; unpack2(acc[j], s0, s1);
            float sp0 = fmaxf(s0, 0.f) + __logf(1.f + __expf(-fabsf(s0)));
            float sp1 = fmaxf(s1, 0.f) + __logf(1.f + __expf(-fabsf(s1)));
            ffma2(rad2, pack2(sp0, sp1), w2u[j]);
        }
        float r0, r1; unpack2(rad2, r0, r1);
        float radial = bias2 + r0 + r1;

        // mask + unit vector + cross with layer_input
        const float* rp = rij + ((size_t)a * NN + b) * 3;
        float rx = rp[0], ry = rp[1], rz = rp[2];
        float d2  = fmaf(rx, rx, fmaf(ry, ry, rz * rz));
        float inv = rsqrtf(fmaxf(d2, 1e-8f));       // norm_with_epsilon
        float m   = (d2 < 1e-16f) ? 0.f : radial;   // dij < 1e-8 mask
        float s   = m * inv;
        float ux = rx * s, uy = ry * s, uz = rz * s;
        float lx = Ls[b * 3 + 0], ly = Ls[b * 3 + 1], lz = Ls[b * 3 + 2];
        o0 = fmaf(uy, lz, o0); o0 = fmaf(-uz, ly, o0);
        o1 = fmaf(uz, lx, o1); o1 = fmaf(-ux, lz, o1);
        o2 = fmaf(ux, ly, o2); o2 = fmaf(-uy, lx, o2);
    }

    // intra-warp reduce, then cross-warp via smem
    #pragma unroll
    for (int off = 16; off > 0; off >>= 1) {
        o0 += __shfl_down_sync(0xffffffffu, o0, off);
        o1 += __shfl_down_sync(0xffffffffu, o1, off);
        o2 += __shfl_down_sync(0xffffffffu, o2, off);
    }
    const int warp = tid >> 5, lane = tid & 31;
    if (lane == 0) { redbuf[0][warp] = o0; redbuf[1][warp] = o1; redbuf[2][warp] = o2; }
    __syncthreads();
    if (tid == 0) {
        float s0 = 0.f, s1 = 0.f, s2 = 0.f;
        #pragma unroll
        for (int w = 0; w < TPB / 32; w++) {
            s0 += redbuf[0][w]; s1 += redbuf[1][w]; s2 += redbuf[2][w];
        }
        out[a * 3 + 0] = s0;
        out[a * 3 + 1] = s1;
        out[a * 3 + 2] = s2;
    }
}

extern "C" void kernel_launch(void* const* d_in, const int* in_sizes, int n_in,
                              void* d_out, int out_size) {
    const float* layer_input = (const float*)d_in[0];
    const float* rbf         = (const float*)d_in[1];
    const float* rij         = (const float*)d_in[2];
    const float* W1          = (const float*)d_in[3];
    const float* b1          = (const float*)d_in[4];
    const float* W2          = (const float*)d_in[5];
    const float* b2          = (const float*)d_in[6];
    float* out = (float*)d_out;

    f1o1_kernel<<<NN, TPB>>>(layer_input, rbf, rij, W1, b1, W2, b2, out);
}

// round 5
// speedup vs baseline: 22.2184x; 1.6722x over previous
#include <cuda_runtime.h>
#include <cuda_bf16.h>

#define NN   2048
#define RBF  32
#define TPB  128
#define WARPS (TPB / 32)
#define ROWS_PER_PASS 64
#define PASSES (NN / (WARPS * ROWS_PER_PASS))   // 8

// ---- f32x2 packed helpers (sm_103a FFMA2 path) ----
__device__ __forceinline__ unsigned long long pack2(float lo, float hi) {
    unsigned long long r;
    asm("mov.b64 %0, {%1, %2};"
        : "=l"(r) : "r"(__float_as_uint(lo)), "r"(__float_as_uint(hi)));
    return r;
}
__device__ __forceinline__ void unpack2(unsigned long long v, float& lo, float& hi) {
    unsigned int l, h;
    asm("mov.b64 {%0, %1}, %2;" : "=r"(l), "=r"(h) : "l"(v));
    lo = __uint_as_float(l); hi = __uint_as_float(h);
}
__device__ __forceinline__ void ffma2(unsigned long long& d,
                                      unsigned long long a, unsigned long long b) {
    asm("fma.rn.f32x2 %0, %1, %2, %3;" : "=l"(d) : "l"(a), "l"(b), "l"(d));
}
__device__ __forceinline__ void cp_async16(unsigned int smem_addr, const void* gptr) {
    asm volatile("cp.async.cg.shared.global [%0], [%1], 16;\n"
                 :: "r"(smem_addr), "l"(gptr) : "memory");
}

// Fused F1-filter. One block per 'a'. Each warp stages 64 rbf rows into a
// swizzled smem tile via cp.async (coalesced: 4 L1 wavefronts/instr instead
// of 32), then each thread computes TWO pairs so each broadcast W1 LDS.128
// feeds 4 f32x2 FMAs.
__global__ __launch_bounds__(TPB, 4) void f1o1_kernel(
    const float* __restrict__ layer_input,  // [NN,1,3]
    const float* __restrict__ rbf,          // [NN,NN,RBF]
    const float* __restrict__ rij,          // [NN,NN,3]
    const float* __restrict__ W1,           // [RBF,RBF] (k,h) row-major
    const float* __restrict__ b1,           // [RBF]
    const float* __restrict__ W2,           // [RBF,1]
    const float* __restrict__ b2,           // [1]
    float* __restrict__ out)                // [NN,1,3]
{
    extern __shared__ __align__(16) float smem[];
    float* w1s   = smem;                         // 1024 floats
    float* tiles = smem + RBF * RBF;             // WARPS * 64*32 floats
    __shared__ float b1s[RBF];
    __shared__ float w2s[RBF];
    __shared__ float redbuf[3][WARPS];

    const int tid  = threadIdx.x;
    const int lane = tid & 31;
    const int warp = tid >> 5;
    const int a    = blockIdx.x;

    for (int i = tid; i < RBF * RBF; i += TPB) w1s[i] = W1[i];
    if (tid < RBF) { b1s[tid] = b1[tid]; w2s[tid] = W2[tid]; }
    __syncthreads();

    const float bias2 = b2[0];
    const unsigned long long* b1u = (const unsigned long long*)b1s;
    const unsigned long long* w2u = (const unsigned long long*)w2s;

    float4* mytile = (float4*)(tiles + warp * (ROWS_PER_PASS * RBF)); // 512 float4
    const unsigned int tile_sbase =
        (unsigned int)__cvta_generic_to_shared(mytile);
    const int s = lane & 7;          // swizzle key (same for rows lane, lane+32)

    float o0 = 0.f, o1 = 0.f, o2 = 0.f;

    #pragma unroll 1
    for (int pass = 0; pass < PASSES; pass++) {
        const int base = (warp * PASSES + pass) * ROWS_PER_PASS;

        // ---- stage 64 rows x 128B, coalesced, swizzled, via cp.async ----
        const float4* g = (const float4*)(rbf + ((size_t)a * NN + base) * RBF);
        #pragma unroll
        for (int j = 0; j < 16; j++) {
            int f = lane + 32 * j;          // float4 index 0..511
            int r = f >> 3, c = f & 7;
            unsigned int dst = tile_sbase + (((r << 3) | (c ^ (r & 7))) << 4);
            cp_async16(dst, g + f);
        }
        asm volatile("cp.async.commit_group;\n" ::: "memory");
        asm volatile("cp.async.wait_group 0;\n" ::: "memory");
        __syncwarp();

        const int b0 = base + lane;
        const int b1i = base + 32 + lane;
        const int r0 = lane, r1 = 32 + lane;

        unsigned long long acc0[RBF / 2], acc1[RBF / 2];
        #pragma unroll
        for (int j = 0; j < RBF / 2; j++) { acc0[j] = b1u[j]; acc1[j] = b1u[j]; }

        // ---- dual-row MLP layer 1: h-pairs packed in f32x2 ----
        #pragma unroll 1
        for (int c = 0; c < 8; c++) {
            float4 x0 = mytile[(r0 << 3) | (c ^ s)];
            float4 x1 = mytile[(r1 << 3) | (c ^ s)];
            #pragma unroll
            for (int kk = 0; kk < 4; kk++) {
                float xv0 = (kk == 0) ? x0.x : (kk == 1) ? x0.y : (kk == 2) ? x0.z : x0.w;
                float xv1 = (kk == 0) ? x1.x : (kk == 1) ? x1.y : (kk == 2) ? x1.z : x1.w;
                unsigned long long xd0 = pack2(xv0, xv0);
                unsigned long long xd1 = pack2(xv1, xv1);
                const ulonglong2* wp = (const ulonglong2*)(w1s + (c * 4 + kk) * RBF);
                #pragma unroll
                for (int jj = 0; jj < 8; jj++) {
                    ulonglong2 w = wp[jj];          // LDS.128 broadcast -> 4 ffma2
                    ffma2(acc0[jj * 2 + 0], xd0, w.x);
                    ffma2(acc0[jj * 2 + 1], xd0, w.y);
                    ffma2(acc1[jj * 2 + 0], xd1, w.x);
                    ffma2(acc1[jj * 2 + 1], xd1, w.y);
                }
            }
        }

        // ---- epilogue for both pairs ----
        #pragma unroll
        for (int p = 0; p < 2; p++) {
            const unsigned long long* acc = p ? acc1 : acc0;
            const int b = p ? b1i : b0;

            unsigned long long rad2 = 0ULL;
            #pragma unroll
            for (int j = 0; j < RBF / 2; j++) {
                float s0, s1; unpack2(acc[j], s0, s1);
                float sp0 = fmaxf(s0, 0.f) + __logf(1.f + __expf(-fabsf(s0)));
                float sp1 = fmaxf(s1, 0.f) + __logf(1.f + __expf(-fabsf(s1)));
                ffma2(rad2, pack2(sp0, sp1), w2u[j]);
            }
            float ra, rb; unpack2(rad2, ra, rb);
            float radial = bias2 + ra + rb;

            const float* rp = rij + ((size_t)a * NN + b) * 3;
            float rx = rp[0], ry = rp[1], rz = rp[2];
            float d2  = fmaf(rx, rx, fmaf(ry, ry, rz * rz));
            float inv = rsqrtf(fmaxf(d2, 1e-8f));       // norm_with_epsilon
            float m   = (d2 < 1e-16f) ? 0.f : radial;   // dij < 1e-8 mask
            float sc  = m * inv;
            float ux = rx * sc, uy = ry * sc, uz = rz * sc;

            const float* lp = layer_input + b * 3;      // L2-hot, coalesced
            float lx = lp[0], ly = lp[1], lz = lp[2];
            o0 = fmaf(uy, lz, o0); o0 = fmaf(-uz, ly, o0);
            o1 = fmaf(uz, lx, o1); o1 = fmaf(-ux, lz, o1);
            o2 = fmaf(ux, ly, o2); o2 = fmaf(-uy, lx, o2);
        }
        __syncwarp();   // tile reuse safety for next pass
    }

    // ---- reduction: intra-warp shuffles, then cross-warp via smem ----
    #pragma unroll
    for (int off = 16; off > 0; off >>= 1) {
        o0 += __shfl_down_sync(0xffffffffu, o0, off);
        o1 += __shfl_down_sync(0xffffffffu, o1, off);
        o2 += __shfl_down_sync(0xffffffffu, o2, off);
    }
    if (lane == 0) { redbuf[0][warp] = o0; redbuf[1][warp] = o1; redbuf[2][warp] = o2; }
    __syncthreads();
    if (tid == 0) {
        float s0 = 0.f, s1 = 0.f, s2 = 0.f;
        #pragma unroll
        for (int w = 0; w < WARPS; w++) {
            s0 += redbuf[0][w]; s1 += redbuf[1][w]; s2 += redbuf[2][w];
        }
        out[a * 3 + 0] = s0;
        out[a * 3 + 1] = s1;
        out[a * 3 + 2] = s2;
    }
}

extern "C" void kernel_launch(void* const* d_in, const int* in_sizes, int n_in,
                              void* d_out, int out_size) {
    const float* layer_input = (const float*)d_in[0];
    const float* rbf         = (const float*)d_in[1];
    const float* rij         = (const float*)d_in[2];
    const float* W1          = (const float*)d_in[3];
    const float* b1          = (const float*)d_in[4];
    const float* W2          = (const float*)d_in[5];
    const float* b2          = (const float*)d_in[6];
    float* out = (float*)d_out;

    size_t shmem = (RBF * RBF + WARPS * ROWS_PER_PASS * RBF) * sizeof(float);
    f1o1_kernel<<<NN, TPB, shmem>>>(layer_input, rbf, rij, W1, b1, W2, b2, out);
}

// round 8
// speedup vs baseline: 38.7023x; 1.7419x over previous
#include <cuda_runtime.h>
#include <cuda_bf16.h>
#include <cstdint>

#define NN      2048
#define RBF     32
#define TPB     128
#define MTILE   128
#define NTILES  (NN / MTILE)   // 16
#define APITCH  80             // bytes per 32-bf16 row; 80/4=20 banks -> 8 rows conflict-free

// ---------------- helpers ----------------
__device__ __forceinline__ uint32_t smem_u32(const void* p) {
    return (uint32_t)__cvta_generic_to_shared(p);
}
__device__ __forceinline__ void cp_async16(uint32_t saddr, const void* g) {
    asm volatile("cp.async.cg.shared.global [%0], [%1], 16;\n"
                 :: "r"(saddr), "l"(g) : "memory");
}
__device__ __forceinline__ void ldmatrix_x4(uint32_t addr, uint32_t& r0, uint32_t& r1,
                                            uint32_t& r2, uint32_t& r3) {
    asm volatile("ldmatrix.sync.aligned.m8n8.x4.shared.b16 {%0,%1,%2,%3}, [%4];"
                 : "=r"(r0), "=r"(r1), "=r"(r2), "=r"(r3) : "r"(addr));
}
__device__ __forceinline__ void ldmatrix_x2(uint32_t addr, uint32_t& r0, uint32_t& r1) {
    asm volatile("ldmatrix.sync.aligned.m8n8.x2.shared.b16 {%0,%1}, [%2];"
                 : "=r"(r0), "=r"(r1) : "r"(addr));
}
__device__ __forceinline__ void mma_bf16(float& d0, float& d1, float& d2, float& d3,
                                         uint32_t a0, uint32_t a1, uint32_t a2, uint32_t a3,
                                         uint32_t b0, uint32_t b1) {
    asm volatile("mma.sync.aligned.m16n8k16.row.col.f32.bf16.bf16.f32 "
                 "{%0,%1,%2,%3}, {%4,%5,%6,%7}, {%8,%9}, {%0,%1,%2,%3};"
                 : "+f"(d0), "+f"(d1), "+f"(d2), "+f"(d3)
                 : "r"(a0), "r"(a1), "r"(a2), "r"(a3), "r"(b0), "r"(b1));
}
__device__ __forceinline__ float softplus(float s) {
    return fmaxf(s, 0.f) + __logf(1.f + __expf(-fabsf(s)));
}
__device__ __forceinline__ uint32_t bits2(__nv_bfloat162 v) {
    return *(uint32_t*)&v;
}

// ---------------- kernel ----------------
// One block per 'a'. 16 M-tiles of 128 pairs:
//   cp.async fp32 rbf tile -> bf16 hi/lo split A tiles (80B pitch) ->
//   mma.sync bf16 (3 split products, 2 K-steps) -> softplus/W2 epilogue on
//   fragments -> mask/unit/cross accumulate. W fragments live in registers.
__global__ __launch_bounds__(TPB, 4) void f1o1_mma_kernel(
    const float* __restrict__ layer_input,  // [NN,1,3]
    const float* __restrict__ rbf,          // [NN,NN,RBF]
    const float* __restrict__ rij,          // [NN,NN,3]
    const float* __restrict__ W1,           // [RBF,RBF] (k,h)
    const float* __restrict__ b1,           // [RBF]
    const float* __restrict__ W2,           // [RBF,1]
    const float* __restrict__ b2,           // [1]
    float* __restrict__ out)                // [NN,1,3]
{
    __shared__ __align__(16) float stag[MTILE * RBF];   // 16 KB fp32 staging
    __shared__ __align__(16) char  AhT[MTILE * APITCH]; // 10 KB bf16 hi
    __shared__ __align__(16) char  AlT[MTILE * APITCH]; // 10 KB bf16 lo
    __shared__ __align__(16) char  BhT[RBF * APITCH];   // 2.5 KB W1^T hi
    __shared__ __align__(16) char  BlT[RBF * APITCH];   // 2.5 KB W1^T lo
    __shared__ float radbuf[TPB / 32][32];
    __shared__ float redbuf[3][TPB / 32];

    const int tid  = threadIdx.x;
    const int lane = tid & 31;
    const int wid  = tid >> 5;
    const int a    = blockIdx.x;
    const uint32_t STAG = smem_u32(stag);
    const uint32_t AH = smem_u32(AhT), AL = smem_u32(AlT);
    const uint32_t BH = smem_u32(BhT), BL = smem_u32(BlT);

    // ---- build B = W1^T split hi/lo (once) ----
    for (int e = tid; e < RBF * RBF; e += TPB) {
        int k = e >> 5, h = e & 31;
        float w = W1[e];
        __nv_bfloat16 hb = __float2bfloat16(w);
        __nv_bfloat16 lb = __float2bfloat16(w - __bfloat162float(hb));
        *(unsigned short*)(BhT + h * APITCH + k * 2) = *(unsigned short*)&hb;
        *(unsigned short*)(BlT + h * APITCH + k * 2) = *(unsigned short*)&lb;
    }

    // ---- per-thread W2/b1 values for the fragment epilogue ----
    float w2v[8], b1v[8];
    #pragma unroll
    for (int j = 0; j < 4; j++)
        #pragma unroll
        for (int i = 0; i < 2; i++) {
            int idx = 8 * j + 2 * (lane & 3) + i;
            w2v[j * 2 + i] = W2[idx];
            b1v[j * 2 + i] = b1[idx];
        }
    const float bias2 = b2[0];

    // ---- prefetch tile 0 ----
    {
        const float4* g = (const float4*)(rbf + (size_t)a * NN * RBF);
        #pragma unroll
        for (int j = 0; j < 8; j++) {
            int f = tid + TPB * j;
            cp_async16(STAG + f * 16, g + f);
        }
        asm volatile("cp.async.commit_group;" ::: "memory");
    }
    __syncthreads();   // B tiles ready

    // ---- preload B fragments: [j][s][reg] for hi and lo ----
    uint32_t bh[4][2][2], bl[4][2][2];
    {
        int l8 = lane & 7, lm = (lane >> 3) & 1;  // lanes 0-15 matter for x2
        #pragma unroll
        for (int j = 0; j < 4; j++)
            #pragma unroll
            for (int s = 0; s < 2; s++) {
                uint32_t off = (uint32_t)((8 * j + l8) * APITCH + (16 * s + 8 * lm) * 2);
                ldmatrix_x2(BH + off, bh[j][s][0], bh[j][s][1]);
                ldmatrix_x2(BL + off, bl[j][s][0], bl[j][s][1]);
            }
    }

    float o0 = 0.f, o1 = 0.f, o2 = 0.f;

    #pragma unroll 1
    for (int t = 0; t < NTILES; t++) {
        asm volatile("cp.async.wait_group 0;" ::: "memory");
        __syncthreads();

        // ---- convert fp32 staging -> bf16 hi/lo A tiles ----
        #pragma unroll
        for (int j = 0; j < 8; j++) {
            int f = tid + TPB * j;
            float4 v = ((const float4*)stag)[f];
            int row = f >> 3, kq = f & 7;
            __nv_bfloat162 h0 = __floats2bfloat162_rn(v.x, v.y);
            __nv_bfloat162 h1 = __floats2bfloat162_rn(v.z, v.w);
            float2 r0 = __bfloat1622float2(h0);
            float2 r1 = __bfloat1622float2(h1);
            __nv_bfloat162 l0 = __floats2bfloat162_rn(v.x - r0.x, v.y - r0.y);
            __nv_bfloat162 l1 = __floats2bfloat162_rn(v.z - r1.x, v.w - r1.y);
            *(uint2*)(AhT + row * APITCH + kq * 8) = make_uint2(bits2(h0), bits2(h1));
            *(uint2*)(AlT + row * APITCH + kq * 8) = make_uint2(bits2(l0), bits2(l1));
        }
        __syncthreads();

        // ---- prefetch next tile while MMA/epilogue run ----
        if (t + 1 < NTILES) {
            const float4* g = (const float4*)(rbf + ((size_t)a * NN + (t + 1) * MTILE) * RBF);
            #pragma unroll
            for (int j = 0; j < 8; j++) {
                int f = tid + TPB * j;
                cp_async16(STAG + f * 16, g + f);
            }
            asm volatile("cp.async.commit_group;" ::: "memory");
        }

        // ---- MMA: hidden = xh*Wh + xl*Wh + xh*Wl ----
        float d[2][4][4];
        #pragma unroll
        for (int ms = 0; ms < 2; ms++)
            #pragma unroll
            for (int j = 0; j < 4; j++)
                #pragma unroll
                for (int r = 0; r < 4; r++) d[ms][j][r] = 0.f;

        #pragma unroll
        for (int ms = 0; ms < 2; ms++) {
            int rowbase = wid * 32 + ms * 16;
            #pragma unroll
            for (int s = 0; s < 2; s++) {
                uint32_t off = (uint32_t)((rowbase + (lane & 15)) * APITCH
                                          + (16 * s + 8 * (lane >> 4)) * 2);
                uint32_t ah0, ah1, ah2, ah3, al0, al1, al2, al3;
                ldmatrix_x4(AH + off, ah0, ah1, ah2, ah3);
                ldmatrix_x4(AL + off, al0, al1, al2, al3);
                #pragma unroll
                for (int j = 0; j < 4; j++) {
                    mma_bf16(d[ms][j][0], d[ms][j][1], d[ms][j][2], d[ms][j][3],
                             ah0, ah1, ah2, ah3, bh[j][s][0], bh[j][s][1]);
                    mma_bf16(d[ms][j][0], d[ms][j][1], d[ms][j][2], d[ms][j][3],
                             al0, al1, al2, al3, bh[j][s][0], bh[j][s][1]);
                    mma_bf16(d[ms][j][0], d[ms][j][1], d[ms][j][2], d[ms][j][3],
                             ah0, ah1, ah2, ah3, bl[j][s][0], bl[j][s][1]);
                }
            }
        }

        // ---- fragment epilogue: softplus + W2 dot, 4-lane group reduce ----
        #pragma unroll
        for (int ms = 0; ms < 2; ms++) {
            float sA = 0.f, sB = 0.f;   // rows g and g+8 of this m-subtile
            #pragma unroll
            for (int j = 0; j < 4; j++) {
                float h0 = d[ms][j][0] + b1v[2 * j];
                float h1 = d[ms][j][1] + b1v[2 * j + 1];
                float h2 = d[ms][j][2] + b1v[2 * j];
                float h3 = d[ms][j][3] + b1v[2 * j + 1];
                sA = fmaf(softplus(h0), w2v[2 * j], sA);
                sA = fmaf(softplus(h1), w2v[2 * j + 1], sA);
                sB = fmaf(softplus(h2), w2v[2 * j], sB);
                sB = fmaf(softplus(h3), w2v[2 * j + 1], sB);
            }
            sA += __shfl_xor_sync(0xffffffffu, sA, 1);
            sA += __shfl_xor_sync(0xffffffffu, sA, 2);
            sB += __shfl_xor_sync(0xffffffffu, sB, 1);
            sB += __shfl_xor_sync(0xffffffffu, sB, 2);
            if ((lane & 3) == 0) {
                radbuf[wid][ms * 16 + (lane >> 2)]     = sA;
                radbuf[wid][ms * 16 + 8 + (lane >> 2)] = sB;
            }
        }
        __syncwarp();

        // ---- per-pair tail: mask + unit + cross ----
        {
            float rad = radbuf[wid][lane] + bias2;
            int b = t * MTILE + wid * 32 + lane;
            const float* rp = rij + ((size_t)a * NN + b) * 3;
            float rx = rp[0], ry = rp[1], rz = rp[2];
            float d2  = fmaf(rx, rx, fmaf(ry, ry, rz * rz));
            float inv = rsqrtf(fmaxf(d2, 1e-8f));      // norm_with_epsilon
            float m   = (d2 < 1e-16f) ? 0.f : rad;     // dij < 1e-8 mask
            float sc  = m * inv;
            float ux = rx * sc, uy = ry * sc, uz = rz * sc;
            const float* lp = layer_input + b * 3;     // L2-hot
            float lx = lp[0], ly = lp[1], lz = lp[2];
            o0 = fmaf(uy, lz, o0); o0 = fmaf(-uz, ly, o0);
            o1 = fmaf(uz, lx, o1); o1 = fmaf(-ux, lz, o1);
            o2 = fmaf(ux, ly, o2); o2 = fmaf(-uy, lx, o2);
        }
        __syncwarp();
    }

    // ---- reduction ----
    #pragma unroll
    for (int off = 16; off > 0; off >>= 1) {
        o0 += __shfl_down_sync(0xffffffffu, o0, off);
        o1 += __shfl_down_sync(0xffffffffu, o1, off);
        o2 += __shfl_down_sync(0xffffffffu, o2, off);
    }
    if (lane == 0) { redbuf[0][wid] = o0; redbuf[1][wid] = o1; redbuf[2][wid] = o2; }
    __syncthreads();
    if (tid == 0) {
        float s0 = 0.f, s1 = 0.f, s2 = 0.f;
        #pragma unroll
        for (int w = 0; w < TPB / 32; w++) {
            s0 += redbuf[0][w]; s1 += redbuf[1][w]; s2 += redbuf[2][w];
        }
        out[a * 3 + 0] = s0;
        out[a * 3 + 1] = s1;
        out[a * 3 + 2] = s2;
    }
}

extern "C" void kernel_launch(void* const* d_in, const int* in_sizes, int n_in,
                              void* d_out, int out_size) {
    const float* layer_input = (const float*)d_in[0];
    const float* rbf         = (const float*)d_in[1];
    const float* rij         = (const float*)d_in[2];
    const float* W1          = (const float*)d_in[3];
    const float* b1          = (const float*)d_in[4];
    const float* W2          = (const float*)d_in[5];
    const float* b2          = (const float*)d_in[6];
    float* out = (float*)d_out;

    f1o1_mma_kernel<<<NN, TPB>>>(layer_input, rbf, rij, W1, b1, W2, b2, out);
}